// round 2
// baseline (speedup 1.0000x reference)
#include <cuda_runtime.h>
#include <cuda_fp16.h>

// Pyramid scratch for levels 1..7 (level 0 = fm read in place, fp32).
// Texels per plane: 256^2+128^2+64^2+32^2+16^2+8^2+4^2 = 87376.
#define PYR_PLANE_TEXELS 87376
#define PYR_PLANE_F4     (PYR_PLANE_TEXELS * 4)
__device__ float4 g_pyr[3 * PYR_PLANE_F4];                 // fp32 chain (sources for box avgs)
__device__ __half g_pyr_h[3 * PYR_PLANE_TEXELS * 16];      // fp16 sampling copy (~8.4MB)

// Texel offset of level l (1..7) within a plane's region.
__constant__ int c_off[8] = {0, 0, 65536, 81920, 86016, 87040, 87296, 87360};

// ---------------------------------------------------------------------------
// helpers
// ---------------------------------------------------------------------------
__device__ __forceinline__ void st_h4(__half* p, float4 v) {
    __half2 a = __floats2half2_rn(v.x, v.y);
    __half2 b = __floats2half2_rn(v.z, v.w);
    uint2 u;
    u.x = *reinterpret_cast<unsigned*>(&a);
    u.y = *reinterpret_cast<unsigned*>(&b);
    *reinterpret_cast<uint2*>(p) = u;
}

__device__ __forceinline__ float4 ld_h4(const __half* p) {
    uint2 u = __ldg(reinterpret_cast<const uint2*>(p));
    __half2 a = *reinterpret_cast<__half2*>(&u.x);
    __half2 b = *reinterpret_cast<__half2*>(&u.y);
    float2 fa = __half22float2(a);
    float2 fb = __half22float2(b);
    return make_float4(fa.x, fa.y, fb.x, fb.y);
}

// ---------------------------------------------------------------------------
// Level 0 (fm, fp32) -> level 1 (fp32 + fp16). One thread per (plane,y,x,c4).
// ---------------------------------------------------------------------------
__global__ void ds1_kernel(const float4* __restrict__ fm) {
    int idx = blockIdx.x * blockDim.x + threadIdx.x;
    if (idx >= 3 * 256 * 256 * 4) return;
    const int c4 = idx & 3;
    int t = idx >> 2;
    const int x = t & 255;
    const int y = (t >> 8) & 255;
    const int plane = t >> 16;

    const float4* src = fm + plane * (512 * 512 * 4);
    const int xi = x << 1, yi = y << 1;
    const float4 a = __ldg(src + (yi * 512 + xi) * 4 + c4);
    const float4 b = __ldg(src + (yi * 512 + xi + 1) * 4 + c4);
    const float4 c = __ldg(src + ((yi + 1) * 512 + xi) * 4 + c4);
    const float4 d = __ldg(src + ((yi + 1) * 512 + xi + 1) * 4 + c4);

    float4 r;
    r.x = (a.x + b.x + c.x + d.x) * 0.25f;
    r.y = (a.y + b.y + c.y + d.y) * 0.25f;
    r.z = (a.z + b.z + c.z + d.z) * 0.25f;
    r.w = (a.w + b.w + c.w + d.w) * 0.25f;

    const int tex = y * 256 + x;                 // c_off[1] == 0
    g_pyr[plane * PYR_PLANE_F4 + tex * 4 + c4] = r;
    st_h4(g_pyr_h + ((size_t)plane * PYR_PLANE_TEXELS + tex) * 16 + c4 * 4, r);
}

// ---------------------------------------------------------------------------
// Levels d0..d0+2 computed directly from fp32 level src_l via box average
// (equivalent to cascaded 2x2 means). Writes fp32 + fp16.
// ---------------------------------------------------------------------------
__global__ void ds_rest_kernel(int src_l, int d0) {
    int idx = blockIdx.x * blockDim.x + threadIdx.x;

    int lev = d0, rem = idx;
    #pragma unroll
    for (int i = 0; i < 3; ++i) {
        int sz = 512 >> (d0 + i);
        int n = 3 * sz * sz * 4;
        if (rem < n) { lev = d0 + i; break; }
        rem -= n;
        if (i == 2) return;   // out of range
    }
    {
        int sz = 512 >> lev;
        int n = 3 * sz * sz * 4;
        if (lev == d0 + 2 && rem >= n) return;
    }

    const int c4 = rem & 3;
    int t = rem >> 2;
    const int shift = 9 - lev;
    const int s = 512 >> lev;
    const int x = t & (s - 1);
    const int y = (t >> shift) & (s - 1);
    const int plane = t >> (2 * shift);

    const int r = 1 << (lev - src_l);
    const int S = 512 >> src_l;
    const float4* src = g_pyr + plane * PYR_PLANE_F4 + c_off[src_l] * 4;

    float4 acc = make_float4(0.f, 0.f, 0.f, 0.f);
    const int xi = x * r, yi = y * r;
    for (int dy = 0; dy < r; ++dy)
        for (int dx = 0; dx < r; ++dx) {
            float4 v = __ldg(src + ((yi + dy) * S + xi + dx) * 4 + c4);
            acc.x += v.x; acc.y += v.y; acc.z += v.z; acc.w += v.w;
        }
    const float inv = 1.0f / (float)(r * r);
    acc.x *= inv; acc.y *= inv; acc.z *= inv; acc.w *= inv;

    const int tex = c_off[lev] + y * s + x;
    g_pyr[plane * PYR_PLANE_F4 + tex * 4 + c4] = acc;
    st_h4(g_pyr_h + ((size_t)plane * PYR_PLANE_TEXELS + tex) * 16 + c4 * 4, acc);
}

// ---------------------------------------------------------------------------
// Bilinear fetch helpers for the sample kernel.
// ---------------------------------------------------------------------------
struct Corners {
    int xa, xb, ya, yb;
    float w00, w01, w10, w11;
};

__device__ __forceinline__ Corners corners(float u, float v, int size) {
    Corners c;
    const float fs = (float)size;
    const float px = u * fs - 0.5f;
    const float py = v * fs - 0.5f;
    const float x0f = floorf(px);
    const float y0f = floorf(py);
    const float fx = px - x0f;
    const float fy = py - y0f;
    const int x0 = (int)x0f;
    const int y0 = (int)y0f;
    const int sm1 = size - 1;
    c.xa = min(max(x0, 0), sm1);
    c.xb = min(max(x0 + 1, 0), sm1);
    c.ya = min(max(y0, 0), sm1);
    c.yb = min(max(y0 + 1, 0), sm1);
    c.w00 = (1.f - fx) * (1.f - fy);
    c.w01 = fx * (1.f - fy);
    c.w10 = (1.f - fx) * fy;
    c.w11 = fx * fy;
    return c;
}

__device__ __forceinline__ float4 blend4(float4 f00, float4 f01, float4 f10,
                                         float4 f11, const Corners& c) {
    float4 r;
    r.x = f00.x * c.w00 + f01.x * c.w01 + f10.x * c.w10 + f11.x * c.w11;
    r.y = f00.y * c.w00 + f01.y * c.w01 + f10.y * c.w10 + f11.y * c.w11;
    r.z = f00.z * c.w00 + f01.z * c.w01 + f10.z * c.w10 + f11.z * c.w11;
    r.w = f00.w * c.w00 + f01.w * c.w01 + f10.w * c.w10 + f11.w * c.w11;
    return r;
}

__device__ __forceinline__ float4 bilin32(const float4* __restrict__ fm,
                                          int plane, float u, float v, int c4) {
    const int size = 512;
    const float4* base = fm + plane * (512 * 512 * 4);
    Corners c = corners(u, v, size);
    float4 f00 = __ldg(base + (c.ya * size + c.xa) * 4 + c4);
    float4 f01 = __ldg(base + (c.ya * size + c.xb) * 4 + c4);
    float4 f10 = __ldg(base + (c.yb * size + c.xa) * 4 + c4);
    float4 f11 = __ldg(base + (c.yb * size + c.xb) * 4 + c4);
    return blend4(f00, f01, f10, f11, c);
}

__device__ __forceinline__ float4 bilin16(int plane, int li, float u, float v,
                                          int c4) {
    const int size = 512 >> li;
    const __half* base = g_pyr_h + ((size_t)plane * PYR_PLANE_TEXELS + c_off[li]) * 16
                         + c4 * 4;
    Corners c = corners(u, v, size);
    float4 f00 = ld_h4(base + (c.ya * size + c.xa) * 16);
    float4 f01 = ld_h4(base + (c.ya * size + c.xb) * 16);
    float4 f10 = ld_h4(base + (c.yb * size + c.xa) * 16);
    float4 f11 = ld_h4(base + (c.yb * size + c.xb) * 16);
    return blend4(f00, f01, f10, f11, c);
}

// ---------------------------------------------------------------------------
// Sampling kernel: one thread per (point, plane, channel-quad), c4 fastest.
// Level l1 = min(l0+1,7) >= 1 always -> fp16 path; l0 == 0 uses fp32 fm.
// ---------------------------------------------------------------------------
__global__ void sample_kernel(const float* __restrict__ xin,
                              const float* __restrict__ level,
                              const float4* __restrict__ fm,
                              float4* __restrict__ out, int N) {
    int idx = blockIdx.x * blockDim.x + threadIdx.x;
    if (idx >= N * 12) return;

    const int c4 = idx & 3;
    int t = idx >> 2;
    const int plane = t % 3;
    const int pt = t / 3;

    const float xv = __ldg(xin + pt * 3 + 0);
    const float yv = __ldg(xin + pt * 3 + 1);
    const float zv = __ldg(xin + pt * 3 + 2);

    float u, v;
    if (plane == 0)      { u = yv; v = zv; }
    else if (plane == 1) { u = xv; v = zv; }
    else                 { u = xv; v = yv; }

    float lvl = __ldg(level + pt);
    lvl = fminf(fmaxf(lvl, 0.f), 7.f);
    const float l0f = floorf(lvl);
    const float f = lvl - l0f;
    const int l0 = (int)l0f;
    const int l1 = min(l0 + 1, 7);

    float4 s0;
    if (l0 == 0) s0 = bilin32(fm, plane, u, v, c4);
    else         s0 = bilin16(plane, l0, u, v, c4);
    float4 s1 = bilin16(plane, l1, u, v, c4);

    float4 r;
    r.x = s0.x + f * (s1.x - s0.x);
    r.y = s0.y + f * (s1.y - s0.y);
    r.z = s0.z + f * (s1.z - s0.z);
    r.w = s0.w + f * (s1.w - s0.w);

    out[pt * 12 + plane * 4 + c4] = r;
}

extern "C" void kernel_launch(void* const* d_in, const int* in_sizes, int n_in,
                              void* d_out, int out_size) {
    const float*  x     = (const float*)d_in[0];
    const float*  level = (const float*)d_in[1];
    const float4* fm    = (const float4*)d_in[2];
    float4* out = (float4*)d_out;
    const int N = in_sizes[0] / 3;

    const int threads = 256;

    // Level 1 from fm
    {
        int total = 3 * 256 * 256 * 4;
        ds1_kernel<<<(total + threads - 1) / threads, threads>>>(fm);
    }
    // Levels 2,3,4 from level 1
    {
        int total = 3 * 4 * (128 * 128 + 64 * 64 + 32 * 32);
        ds_rest_kernel<<<(total + threads - 1) / threads, threads>>>(1, 2);
    }
    // Levels 5,6,7 from level 4
    {
        int total = 3 * 4 * (16 * 16 + 8 * 8 + 4 * 4);
        ds_rest_kernel<<<(total + threads - 1) / threads, threads>>>(4, 5);
    }
    // Sample
    {
        int total = N * 12;
        sample_kernel<<<(total + threads - 1) / threads, threads>>>(x, level, fm, out, N);
    }
}